// round 15
// baseline (speedup 1.0000x reference)
#include <cuda_runtime.h>
#include <cuda_fp16.h>
#include <cstdint>

// ChebConv, commuted:
//   Agg[row, j*64+k] = sum_{e: rows[e]=row} vals[e] * xh[512*cols[e] + j*64 + k]
//   out[(row*8+j)*192 + q] = sum_k Agg[row,j,k] * w[k*192+q] + bias[q&63]
// fp16 gather via chunked double-buffered cp.async; HMMA phase 2; fp32 accumulation.
#define N_VERTEX 2048
#define NNZ_MAX  98304
#define KCOLS    192
#define NSUB     4
#define SUB_CAP  48
#define SLOTS    (NSUB * SUB_CAP)
#define X_ELEMS  3145728
#define SCAT_BLK 384
#define WFRAG_N  6144
#define WFRAG_BLK 24
#define ASTR     72            // sAh row stride (halfs)
#define CH       16            // edges per cp.async chunk (16KB per buffer)

__device__ int    g_cnt[N_VERTEX * NSUB];
__device__ float2 g_edge[N_VERTEX * NSUB * SUB_CAP];
__device__ __align__(16) __half   g_xh[X_ELEMS];       // 6MB fp16 x
__device__ __align__(16) unsigned g_wfrag[WFRAG_N];    // 24KB precomputed B fragments

__device__ __forceinline__ void mma16816(float& c0, float& c1, float& c2, float& c3,
                                         unsigned a0, unsigned a1, unsigned a2, unsigned a3,
                                         unsigned b0, unsigned b1) {
    asm volatile("mma.sync.aligned.m16n8k16.row.col.f32.f16.f16.f32 "
                 "{%0,%1,%2,%3}, {%4,%5,%6,%7}, {%8,%9}, {%0,%1,%2,%3};"
                 : "+f"(c0), "+f"(c1), "+f"(c2), "+f"(c3)
                 : "r"(a0), "r"(a1), "r"(a2), "r"(a3), "r"(b0), "r"(b1));
}

// Fused prepass: [0,384) edge scatter; [384,408) w B-fragment precompute; rest x->fp16.
__global__ void k_prep(const float* __restrict__ x,
                       const float* __restrict__ wf,
                       const float* __restrict__ vals,
                       const int*   __restrict__ rows,
                       const int*   __restrict__ cols, int nnz) {
    if (blockIdx.x < SCAT_BLK) {
        int i = blockIdx.x * blockDim.x + threadIdx.x;
        if (i < nnz) {
            int r   = rows[i];
            int sub = i & (NSUB - 1);
            int p   = atomicAdd(&g_cnt[r * NSUB + sub], 1);
            if (p < SUB_CAP)
                g_edge[(r * NSUB + sub) * SUB_CAP + p] =
                    make_float2(vals[i], __int_as_float(cols[i] * 1024));
        }
    } else if (blockIdx.x < SCAT_BLK + WFRAG_BLK) {
        // B fragment for mma.m16n8k16.row.col: thread holds {B[k][n], B[k+1][n]},
        // fid = ntw*256 + lane*8 + (2*kt + h); k = 16*kt + 8*h + 2*(lane&3), n = 8*ntw + lane/4.
        int fid  = (blockIdx.x - SCAT_BLK) * 256 + threadIdx.x;   // < 6144
        int r    = fid & 7;
        int lane = (fid >> 3) & 31;
        int ntw  = fid >> 8;
        int kt   = r >> 1, h = r & 1;
        int k = 16 * kt + 8 * h + 2 * (lane & 3);
        int n = 8 * ntw + (lane >> 2);
        __half2 v = __floats2half2_rn(wf[k * KCOLS + n], wf[(k + 1) * KCOLS + n]);
        g_wfrag[fid] = *reinterpret_cast<unsigned*>(&v);
    } else {
        int i = (blockIdx.x - SCAT_BLK - WFRAG_BLK) * blockDim.x + threadIdx.x;
        if (i < X_ELEMS / 8) {
            float4 v0 = reinterpret_cast<const float4*>(x)[2 * i];
            float4 v1 = reinterpret_cast<const float4*>(x)[2 * i + 1];
            __half2 h0 = __floats2half2_rn(v0.x, v0.y);
            __half2 h1 = __floats2half2_rn(v0.z, v0.w);
            __half2 h2 = __floats2half2_rn(v1.x, v1.y);
            __half2 h3 = __floats2half2_rn(v1.z, v1.w);
            uint4 p;
            p.x = *reinterpret_cast<unsigned*>(&h0);
            p.y = *reinterpret_cast<unsigned*>(&h1);
            p.z = *reinterpret_cast<unsigned*>(&h2);
            p.w = *reinterpret_cast<unsigned*>(&h3);
            reinterpret_cast<uint4*>(g_xh)[i] = p;
        }
    }
}

// Fused per-row kernel: cp.async gather pipeline -> fp16 smem Agg -> HMMA.
__global__ __launch_bounds__(256) void k_main(
    const float* __restrict__ bias,
    float* __restrict__ out)
{
    __shared__ __align__(16) char   sBuf[2][CH * 1024];   // 2 x 16KB slice buffers
    __shared__ __align__(16) __half sAh[8 * ASTR];        // fp16 Agg, rows j=0..7
    __shared__ float2 sE[SLOTS];
    __shared__ int    sCnt[NSUB];

    const int row = blockIdx.x;
    const int tid = threadIdx.x;

    if (tid < NSUB) {
        int c = g_cnt[row * NSUB + tid];
        sCnt[tid] = (c > SUB_CAP) ? SUB_CAP : c;
        g_cnt[row * NSUB + tid] = 0;                    // restore invariant for replay
    }
    __syncthreads();
    const int c0 = sCnt[0], c1 = sCnt[1], c2 = sCnt[2], c3 = sCnt[3];
    const int deg = c0 + c1 + c2 + c3;                  // <= 192

    if (tid < deg) {
        int b, pos;
        if      (tid < c0)           { b = 0; pos = tid; }
        else if (tid < c0 + c1)      { b = 1; pos = tid - c0; }
        else if (tid < c0 + c1 + c2) { b = 2; pos = tid - c0 - c1; }
        else                         { b = 3; pos = tid - c0 - c1 - c2; }
        sE[tid] = g_edge[(row * NSUB + b) * SUB_CAP + pos];
    }
    __syncthreads();

    // ---- Phase 1: chunked double-buffered cp.async gather + smem accumulate ----
    const int nCh = (deg + CH - 1) / CH;
    float acc0 = 0.f, acc1 = 0.f;                       // thread owns halfs 2t, 2t+1

    // issue chunk: CH edges x 64 segs of 16B = 1024 copies, 4 per thread.
    // dst byte = e_local*1024 + seg*16; src = xh + col*1024 + seg*16.
    #define ISSUE_CHUNK(cIdx)                                                        \
        do {                                                                         \
            char* dstb = sBuf[(cIdx) & 1];                                           \
            const int eBase = (cIdx) * CH;                                           \
            _Pragma("unroll")                                                        \
            for (int it = 0; it < 4; ++it) {                                         \
                int idx = tid + 256 * it;                                            \
                int e   = eBase + (idx >> 6);                                        \
                if (e < deg) {                                                       \
                    const char* src = (const char*)g_xh +                            \
                        __float_as_int(sE[e].y) + ((idx & 63) << 4);                 \
                    unsigned sdst = (unsigned)__cvta_generic_to_shared(              \
                        dstb + (idx << 4));                                          \
                    asm volatile("cp.async.cg.shared.global [%0], [%1], 16;"         \
                                 :: "r"(sdst), "l"(src));                            \
                }                                                                    \
            }                                                                        \
            asm volatile("cp.async.commit_group;" ::: "memory");                     \
        } while (0)

    if (nCh > 0) ISSUE_CHUNK(0);
    for (int c = 0; c < nCh; ++c) {
        if (c + 1 < nCh) {
            ISSUE_CHUNK(c + 1);
            asm volatile("cp.async.wait_group 1;" ::: "memory");
        } else {
            asm volatile("cp.async.wait_group 0;" ::: "memory");
        }
        __syncthreads();                               // chunk c visible to all
        const int e0 = c * CH;
        const int e1 = (deg < e0 + CH) ? deg : e0 + CH;
        // slice e_local = 1024B = 256 half2; thread reads half2 index tid within slice
        const __half2* base = reinterpret_cast<const __half2*>(sBuf[c & 1]) + tid;
        #pragma unroll 4
        for (int e = e0; e < e1; ++e) {
            float  v = sE[e].x;                        // LDS.64 broadcast
            __half2 h = base[(e - e0) * 256];          // conflict-free LDS.32
            float2 f = __half22float2(h);
            acc0 = fmaf(v, f.x, acc0);
            acc1 = fmaf(v, f.y, acc1);
        }
        __syncthreads();                               // buffer reusable
    }
    #undef ISSUE_CHUNK

    // write fp16 Agg: f=2*tid -> j=tid>>5 (uniform per warp), k=(2*tid)&63
    {
        __half2 h = __floats2half2_rn(acc0, acc1);
        *reinterpret_cast<__half2*>(&sAh[(tid >> 5) * ASTR + ((2 * tid) & 63)]) = h;
    }
    __syncthreads();

    // ---- Phase 2: A[8(pad16),64] @ W[64,192] via HMMA; warps 0-5, 32 cols each ----
    const int warp = tid >> 5;
    if (warp < 6) {
        const int lane = tid & 31;
        const int j    = lane >> 2;
        const int l4   = lane & 3;

        unsigned afr[4][2];
        #pragma unroll
        for (int kt = 0; kt < 4; ++kt) {
            afr[kt][0] = *reinterpret_cast<const unsigned*>(&sAh[j * ASTR + kt * 16 + 2 * l4]);
            afr[kt][1] = *reinterpret_cast<const unsigned*>(&sAh[j * ASTR + kt * 16 + 8 + 2 * l4]);
        }

        float* orow = out + (size_t)(row * 8 + j) * KCOLS;
        #pragma unroll
        for (int nt = 0; nt < 4; ++nt) {
            const uint4* fp = reinterpret_cast<const uint4*>(
                &g_wfrag[((warp * 4 + nt) * 32 + lane) * 8]);
            uint4 blo = __ldg(fp);
            uint4 bhi = __ldg(fp + 1);
            float d0 = 0.f, d1 = 0.f, d2 = 0.f, d3 = 0.f;
            mma16816(d0, d1, d2, d3, afr[0][0], 0u, afr[0][1], 0u, blo.x, blo.y);
            mma16816(d0, d1, d2, d3, afr[1][0], 0u, afr[1][1], 0u, blo.z, blo.w);
            mma16816(d0, d1, d2, d3, afr[2][0], 0u, afr[2][1], 0u, bhi.x, bhi.y);
            mma16816(d0, d1, d2, d3, afr[3][0], 0u, afr[3][1], 0u, bhi.z, bhi.w);
            const int q = 32 * warp + 8 * nt + 2 * l4;
            float b0 = __ldg(&bias[q & 63]);
            float b1 = __ldg(&bias[(q + 1) & 63]);
            *(float2*)(orow + q) = make_float2(d0 + b0, d1 + b1);
        }
    }
}

extern "C" void kernel_launch(void* const* d_in, const int* in_sizes, int n_in,
                              void* d_out, int out_size) {
    const float* x    = (const float*)d_in[0];
    const float* w    = (const float*)d_in[1];
    const float* bias = (const float*)d_in[2];
    const float* fv   = (const float*)d_in[3];
    const int*   fr   = (const int*)d_in[4];
    const int*   fc   = (const int*)d_in[5];
    int nnz = in_sizes[3];
    if (nnz > NNZ_MAX) nnz = NNZ_MAX;
    float* out = (float*)d_out;

    const int conv_blocks = (X_ELEMS / 8 + 255) / 256;   // 1536
    k_prep<<<SCAT_BLK + WFRAG_BLK + conv_blocks, 256>>>(x, w, fv, fr, fc, nnz);
    k_main<<<N_VERTEX, 256>>>(bias, out);
}